// round 3
// baseline (speedup 1.0000x reference)
#include <cuda_runtime.h>
#include <cuda_bf16.h>
#include <math.h>
#include <stdint.h>

// Problem constants
#define SB   2048
#define BB   2
#define DD   1024
#define NH   16
#define HDIM 64
#define MR   (BB*SB)       // 4096

// Scratch (device globals)
__device__ float g_q[(size_t)BB*NH*SB*HDIM];   // [b,h,s,hd] fp32
__device__ float g_k[(size_t)BB*NH*SB*HDIM];
__device__ float g_v[(size_t)BB*NH*SB*HDIM];
__device__ __align__(256) __nv_bfloat16 g_xhi[(size_t)MR*DD];
__device__ __align__(256) __nv_bfloat16 g_xlo[(size_t)MR*DD];
__device__ __align__(256) __nv_bfloat16 g_whi[4][(size_t)DD*DD];
__device__ __align__(256) __nv_bfloat16 g_wlo[4][(size_t)DD*DD];
__device__ __align__(256) __nv_bfloat16 g_chi[(size_t)MR*DD];   // ctx hi
__device__ __align__(256) __nv_bfloat16 g_clo[(size_t)MR*DD];   // ctx lo

// ===========================================================================
// Helpers: mma.sync / ldmatrix / cp.async (sm_80+ features, assemble on sm_103)
// ===========================================================================
__device__ __forceinline__ uint32_t smem_u32(const void* p) {
    uint32_t a;
    asm("{ .reg .u64 t; cvta.to.shared.u64 t, %1; cvt.u32.u64 %0, t; }"
        : "=r"(a) : "l"(p));
    return a;
}

__device__ __forceinline__ void ldsm4(uint32_t* r, uint32_t a) {
    asm volatile("ldmatrix.sync.aligned.m8n8.x4.shared.b16 {%0,%1,%2,%3}, [%4];"
                 : "=r"(r[0]), "=r"(r[1]), "=r"(r[2]), "=r"(r[3]) : "r"(a));
}

__device__ __forceinline__ void mma16816(float* c, const uint32_t* a, const uint32_t* b) {
    asm volatile(
        "mma.sync.aligned.m16n8k16.row.col.f32.bf16.bf16.f32 "
        "{%0,%1,%2,%3}, {%4,%5,%6,%7}, {%8,%9}, {%0,%1,%2,%3};"
        : "+f"(c[0]), "+f"(c[1]), "+f"(c[2]), "+f"(c[3])
        : "r"(a[0]), "r"(a[1]), "r"(a[2]), "r"(a[3]), "r"(b[0]), "r"(b[1]));
}

__device__ __forceinline__ void cp16(uint32_t dst, const void* src) {
    asm volatile("cp.async.cg.shared.global [%0], [%1], 16;"
                 :: "r"(dst), "l"(src) : "memory");
}
#define CP_COMMIT asm volatile("cp.async.commit_group;" ::: "memory")
#define CP_WAIT0  asm volatile("cp.async.wait_group 0;"  ::: "memory")

__device__ __forceinline__ uint32_t pack2(__nv_bfloat16 a, __nv_bfloat16 b) {
    __nv_bfloat162 t = __halves2bfloat162(a, b);
    return *(uint32_t*)&t;
}

// ===========================================================================
// Split-convert fp32 -> bf16 hi + bf16 lo
// ===========================================================================
__global__ void convert_split(const float* __restrict__ src, int which, int n4)
{
    __nv_bfloat16 *hi, *lo;
    switch (which) {
        case 0: hi = g_xhi;    lo = g_xlo;    break;
        case 1: hi = g_whi[0]; lo = g_wlo[0]; break;
        case 2: hi = g_whi[1]; lo = g_wlo[1]; break;
        case 3: hi = g_whi[2]; lo = g_wlo[2]; break;
        default: hi = g_whi[3]; lo = g_wlo[3]; break;
    }
    for (int i = blockIdx.x * blockDim.x + threadIdx.x; i < n4;
         i += gridDim.x * blockDim.x) {
        float4 v = ((const float4*)src)[i];
        __nv_bfloat16 h0 = __float2bfloat16(v.x);
        __nv_bfloat16 h1 = __float2bfloat16(v.y);
        __nv_bfloat16 h2 = __float2bfloat16(v.z);
        __nv_bfloat16 h3 = __float2bfloat16(v.w);
        uint2 ho = make_uint2(pack2(h0, h1), pack2(h2, h3));
        __nv_bfloat16 l0 = __float2bfloat16(v.x - __bfloat162float(h0));
        __nv_bfloat16 l1 = __float2bfloat16(v.y - __bfloat162float(h1));
        __nv_bfloat16 l2 = __float2bfloat16(v.z - __bfloat162float(h2));
        __nv_bfloat16 l3 = __float2bfloat16(v.w - __bfloat162float(h3));
        uint2 lov = make_uint2(pack2(l0, l1), pack2(l2, l3));
        ((uint2*)hi)[i] = ho;
        ((uint2*)lo)[i] = lov;
    }
}

// ===========================================================================
// Tensor-core GEMM mainloop (mma.sync bf16, 3-term split, fp32 accum).
// D[128,128] = A[128rows m0..]  dot  B[128rows n0..]^T over K=1024.
// 8 warps as 2(m) x 4(n), warp tile 64x32. K-step 32, double-buffered cp.async.
// smem tile layout: 128 rows x 40-half pitch (80B) -> conflict-free ldmatrix.
// ===========================================================================
#define PITCH_H     40
#define TILE_B      (128*PITCH_H*2)     // 10240
#define STAGE_B     (4*TILE_B)          // 40960
#define GSMEM       (2*STAGE_B)         // 81920

__device__ __forceinline__ void gemm_mainloop(
    const __nv_bfloat16* __restrict__ Ahi, const __nv_bfloat16* __restrict__ Alo,
    const __nv_bfloat16* __restrict__ Bhi, const __nv_bfloat16* __restrict__ Blo,
    int m0, int n0, char* sm, float acc[4][4][4])
{
    const int tid = threadIdx.x;
    const uint32_t smb = smem_u32(sm);

    #pragma unroll
    for (int t = 0; t < 4; t++)
        #pragma unroll
        for (int n = 0; n < 4; n++)
            #pragma unroll
            for (int e = 0; e < 4; e++) acc[t][n][e] = 0.0f;

    // stage loader: 4 tiles x 512 16B-chunks, 2 chunks/thread/tile
    auto load_stage = [&](int st, int k0) {
        uint32_t base = smb + st * STAGE_B;
        #pragma unroll
        for (int j = 0; j < 2; j++) {
            int idx = tid + j * 256;
            int r = idx >> 2, c = idx & 3;
            uint32_t doff = r * (PITCH_H*2) + c * 16;
            size_t sa = (size_t)(m0 + r) * DD + k0 + c * 8;
            size_t sb = (size_t)(n0 + r) * DD + k0 + c * 8;
            cp16(base + doff,            Ahi + sa);
            cp16(base + TILE_B + doff,   Alo + sa);
            cp16(base + 2*TILE_B + doff, Bhi + sb);
            cp16(base + 3*TILE_B + doff, Blo + sb);
        }
    };

    load_stage(0, 0);
    CP_COMMIT;

    const int wid = tid >> 5, lane = tid & 31;
    const int wm = (wid >> 2) * 64;
    const int wn = (wid & 3) * 32;
    // ldmatrix lane->address mapping
    const int arow = lane & 15;                       // + wm + t*16
    const int akk  = (lane >> 4) << 3;                // + ko
    const int brow = (lane & 7) + ((lane >> 4) << 3); // + wn + p*16
    const int bkk  = ((lane >> 3) & 1) << 3;          // + ko

    for (int kt = 0; kt < 32; kt++) {
        CP_WAIT0;
        __syncthreads();
        if (kt + 1 < 32) { load_stage((kt + 1) & 1, (kt + 1) * 32); CP_COMMIT; }

        uint32_t base = smb + (kt & 1) * STAGE_B;
        uint32_t sAh = base, sAl = base + TILE_B;
        uint32_t sBh = base + 2*TILE_B, sBl = base + 3*TILE_B;

        #pragma unroll
        for (int k16 = 0; k16 < 2; k16++) {
            const int ko = k16 * 16;
            uint32_t ah[4][4], al[4][4], bh[4][2], bl[4][2];
            #pragma unroll
            for (int t = 0; t < 4; t++) {
                uint32_t ao = (uint32_t)((wm + t*16 + arow) * (PITCH_H*2) + (ko + akk) * 2);
                ldsm4(ah[t], sAh + ao);
                ldsm4(al[t], sAl + ao);
            }
            #pragma unroll
            for (int p = 0; p < 2; p++) {
                uint32_t bo = (uint32_t)((wn + p*16 + brow) * (PITCH_H*2) + (ko + bkk) * 2);
                uint32_t r4[4];
                ldsm4(r4, sBh + bo);
                bh[2*p][0] = r4[0]; bh[2*p][1] = r4[1];
                bh[2*p+1][0] = r4[2]; bh[2*p+1][1] = r4[3];
                ldsm4(r4, sBl + bo);
                bl[2*p][0] = r4[0]; bl[2*p][1] = r4[1];
                bl[2*p+1][0] = r4[2]; bl[2*p+1][1] = r4[3];
            }
            #pragma unroll
            for (int t = 0; t < 4; t++)
                #pragma unroll
                for (int n = 0; n < 4; n++) {
                    mma16816(acc[t][n], ah[t], bh[n]);
                    mma16816(acc[t][n], ah[t], bl[n]);
                    mma16816(acc[t][n], al[t], bh[n]);
                }
        }
    }
}

// ---------------------------------------------------------------------------
// QKV projection on tensor pipe. Writes fp32 [b,h,s,hd].
// ---------------------------------------------------------------------------
__global__ __launch_bounds__(256) void qkv_gemm_mma()
{
    extern __shared__ char sm[];
    const int n0g = blockIdx.x * 128;
    const int m0  = blockIdx.y * 128;
    const int which = n0g >> 10;
    const int nb    = n0g & 1023;

    float* OUT = (which == 0) ? g_q : (which == 1 ? g_k : g_v);

    float acc[4][4][4];
    gemm_mainloop(g_xhi, g_xlo, g_whi[which], g_wlo[which], m0, nb, sm, acc);

    const int tid = threadIdx.x, wid = tid >> 5, lane = tid & 31;
    const int wm = (wid >> 2) * 64, wn = (wid & 3) * 32;
    const int gid = lane >> 2, qid = lane & 3;

    #pragma unroll
    for (int t = 0; t < 4; t++) {
        #pragma unroll
        for (int n = 0; n < 4; n++) {
            int cc = nb + wn + n*8 + qid*2;
            int h = cc >> 6, hd = cc & 63;
            #pragma unroll
            for (int half = 0; half < 2; half++) {
                int row = m0 + wm + t*16 + gid + 8*half;
                int b = row >> 11, s = row & 2047;
                float2 v = make_float2(acc[t][n][2*half], acc[t][n][2*half + 1]);
                *(float2*)&OUT[(((size_t)(b*NH + h))*SB + s)*HDIM + hd] = v;
            }
        }
    }
}

// ---------------------------------------------------------------------------
// Output projection: out = ctx @ Wo^T + bo
// ---------------------------------------------------------------------------
__global__ __launch_bounds__(256) void out_gemm_mma(
    const float* __restrict__ bo, float* __restrict__ OUT)
{
    extern __shared__ char sm[];
    const int n0 = blockIdx.x * 128;
    const int m0 = blockIdx.y * 128;

    float acc[4][4][4];
    gemm_mainloop(g_chi, g_clo, g_whi[3], g_wlo[3], m0, n0, sm, acc);

    const int tid = threadIdx.x, wid = tid >> 5, lane = tid & 31;
    const int wm = (wid >> 2) * 64, wn = (wid & 3) * 32;
    const int gid = lane >> 2, qid = lane & 3;

    #pragma unroll
    for (int t = 0; t < 4; t++) {
        #pragma unroll
        for (int n = 0; n < 4; n++) {
            int cn = n0 + wn + n*8 + qid*2;
            float2 bb = *(const float2*)&bo[cn];
            #pragma unroll
            for (int half = 0; half < 2; half++) {
                int row = m0 + wm + t*16 + gid + 8*half;
                float2 v = make_float2(acc[t][n][2*half] + bb.x,
                                       acc[t][n][2*half + 1] + bb.y);
                *(float2*)&OUT[(size_t)row * DD + cn] = v;
            }
        }
    }
}

// ---------------------------------------------------------------------------
// Flash attention, causal, fp32 (unchanged core). Epilogue writes bf16 hi/lo.
// ---------------------------------------------------------------------------
__global__ __launch_bounds__(256) void flash_attn()
{
    __shared__ float Qs[64][65];
    __shared__ float Ks[64][65];
    __shared__ float Vs[64][65];
    __shared__ float Ps[64][65];

    const int qt = blockIdx.x;
    const int bh = blockIdx.y;
    const int q0 = qt * 64;

    const float* __restrict__ Qp = g_q + ((size_t)bh*SB + q0)*HDIM;
    const float* __restrict__ Kp = g_k + (size_t)bh*SB*HDIM;
    const float* __restrict__ Vp = g_v + (size_t)bh*SB*HDIM;

    const int tid = threadIdx.x;
    const int tx = tid & 15, ty = tid >> 4;

    for (int t = tid; t < 64*64; t += 256) {
        int r = t >> 6, d = t & 63;
        Qs[r][d] = Qp[t];
    }

    float m_i[4], l_i[4], o[4][4];
    #pragma unroll
    for (int i = 0; i < 4; i++) {
        m_i[i] = -INFINITY; l_i[i] = 0.0f;
        #pragma unroll
        for (int j = 0; j < 4; j++) o[i][j] = 0.0f;
    }

    for (int kt = 0; kt <= qt; kt++) {
        const int c0 = kt * 64;
        __syncthreads();
        for (int t = tid; t < 64*64; t += 256) {
            int r = t >> 6, d = t & 63;
            Ks[r][d] = Kp[(size_t)(c0 + r)*HDIM + d];
            Vs[r][d] = Vp[(size_t)(c0 + r)*HDIM + d];
        }
        __syncthreads();

        float s[4][4];
        #pragma unroll
        for (int i = 0; i < 4; i++)
            #pragma unroll
            for (int j = 0; j < 4; j++) s[i][j] = 0.0f;
        #pragma unroll 4
        for (int d = 0; d < 64; d++) {
            float qv[4], kv[4];
            #pragma unroll
            for (int i = 0; i < 4; i++) qv[i] = Qs[ty + 16*i][d];
            #pragma unroll
            for (int j = 0; j < 4; j++) kv[j] = Ks[tx + 16*j][d];
            #pragma unroll
            for (int i = 0; i < 4; i++)
                #pragma unroll
                for (int j = 0; j < 4; j++)
                    s[i][j] = fmaf(qv[i], kv[j], s[i][j]);
        }

        const bool diag = (kt == qt);
        #pragma unroll
        for (int i = 0; i < 4; i++) {
            int r = ty + 16*i;
            #pragma unroll
            for (int j = 0; j < 4; j++) {
                int c = tx + 16*j;
                float sv = s[i][j] * 0.125f;
                if (diag && c > r) sv = -INFINITY;
                s[i][j] = sv;
            }
        }

        float rm[4], rs[4], mn[4], al[4];
        #pragma unroll
        for (int i = 0; i < 4; i++)
            rm[i] = fmaxf(fmaxf(s[i][0], s[i][1]), fmaxf(s[i][2], s[i][3]));
        #pragma unroll
        for (int msk = 8; msk >= 1; msk >>= 1)
            #pragma unroll
            for (int i = 0; i < 4; i++)
                rm[i] = fmaxf(rm[i], __shfl_xor_sync(0xffffffffu, rm[i], msk));
        #pragma unroll
        for (int i = 0; i < 4; i++) {
            mn[i] = fmaxf(m_i[i], rm[i]);
            al[i] = __expf(m_i[i] - mn[i]);
            rs[i] = 0.0f;
            #pragma unroll
            for (int j = 0; j < 4; j++) {
                s[i][j] = __expf(s[i][j] - mn[i]);
                rs[i] += s[i][j];
            }
        }
        #pragma unroll
        for (int msk = 8; msk >= 1; msk >>= 1)
            #pragma unroll
            for (int i = 0; i < 4; i++)
                rs[i] += __shfl_xor_sync(0xffffffffu, rs[i], msk);
        #pragma unroll
        for (int i = 0; i < 4; i++) {
            l_i[i] = l_i[i] * al[i] + rs[i];
            m_i[i] = mn[i];
            #pragma unroll
            for (int j = 0; j < 4; j++) {
                o[i][j] *= al[i];
                Ps[ty + 16*i][tx + 16*j] = s[i][j];
            }
        }
        __syncthreads();

        #pragma unroll 4
        for (int c = 0; c < 64; c++) {
            float pv[4], vv[4];
            #pragma unroll
            for (int i = 0; i < 4; i++) pv[i] = Ps[ty + 16*i][c];
            #pragma unroll
            for (int j = 0; j < 4; j++) vv[j] = Vs[c][tx + 16*j];
            #pragma unroll
            for (int i = 0; i < 4; i++)
                #pragma unroll
                for (int j = 0; j < 4; j++)
                    o[i][j] = fmaf(pv[i], vv[j], o[i][j]);
        }
    }

    const int b = bh / NH, h = bh % NH;
    #pragma unroll
    for (int i = 0; i < 4; i++) {
        int r = ty + 16*i;
        float inv = 1.0f / l_i[i];
        #pragma unroll
        for (int j = 0; j < 4; j++) {
            int dd = tx + 16*j;
            float val = o[i][j] * inv;
            __nv_bfloat16 hh = __float2bfloat16(val);
            __nv_bfloat16 ll = __float2bfloat16(val - __bfloat162float(hh));
            size_t off = ((size_t)(b*SB + q0 + r))*DD + h*HDIM + dd;
            g_chi[off] = hh;
            g_clo[off] = ll;
        }
    }
}

// ---------------------------------------------------------------------------
extern "C" void kernel_launch(void* const* d_in, const int* in_sizes, int n_in,
                              void* d_out, int out_size)
{
    const float* x  = (const float*)d_in[0];
    const float* Wq = (const float*)d_in[1];
    const float* Wk = (const float*)d_in[2];
    const float* Wv = (const float*)d_in[3];
    const float* Wo = (const float*)d_in[4];
    const float* bo = (const float*)d_in[5];
    float* out = (float*)d_out;

    cudaFuncSetAttribute(qkv_gemm_mma, cudaFuncAttributeMaxDynamicSharedMemorySize, GSMEM);
    cudaFuncSetAttribute(out_gemm_mma, cudaFuncAttributeMaxDynamicSharedMemorySize, GSMEM);

    convert_split<<<512, 256>>>(x,  0, MR*DD/4);
    convert_split<<<256, 256>>>(Wq, 1, DD*DD/4);
    convert_split<<<256, 256>>>(Wk, 2, DD*DD/4);
    convert_split<<<256, 256>>>(Wv, 3, DD*DD/4);
    convert_split<<<256, 256>>>(Wo, 4, DD*DD/4);

    qkv_gemm_mma<<<dim3(24, 32), 256, GSMEM>>>();
    flash_attn<<<dim3(SB/64, BB*NH), 256>>>();
    out_gemm_mma<<<dim3(8, 32), 256, GSMEM>>>(bo, out);
}

// round 4
// speedup vs baseline: 1.8140x; 1.8140x over previous
#include <cuda_runtime.h>
#include <cuda_bf16.h>
#include <math.h>
#include <stdint.h>

// Problem constants
#define SB   2048
#define BB   2
#define DD   1024
#define NH   16
#define HDIM 64
#define MR   (BB*SB)       // 4096

// Scratch (device globals)
__device__ float g_q[(size_t)BB*NH*SB*HDIM];   // [b,h,s,hd] fp32
__device__ float g_k[(size_t)BB*NH*SB*HDIM];
__device__ float g_v[(size_t)BB*NH*SB*HDIM];
__device__ __align__(256) __nv_bfloat16 g_xhi[(size_t)MR*DD];
__device__ __align__(256) __nv_bfloat16 g_xlo[(size_t)MR*DD];
__device__ __align__(256) __nv_bfloat16 g_whi[4][(size_t)DD*DD];
__device__ __align__(256) __nv_bfloat16 g_wlo[4][(size_t)DD*DD];
__device__ __align__(256) __nv_bfloat16 g_chi[(size_t)MR*DD];   // ctx hi
__device__ __align__(256) __nv_bfloat16 g_clo[(size_t)MR*DD];   // ctx lo

// ===========================================================================
// Helpers
// ===========================================================================
__device__ __forceinline__ uint32_t smem_u32(const void* p) {
    uint32_t a;
    asm("{ .reg .u64 t; cvta.to.shared.u64 t, %1; cvt.u32.u64 %0, t; }"
        : "=r"(a) : "l"(p));
    return a;
}

__device__ __forceinline__ void ldsm4(uint32_t* r, uint32_t a) {
    asm volatile("ldmatrix.sync.aligned.m8n8.x4.shared.b16 {%0,%1,%2,%3}, [%4];"
                 : "=r"(r[0]), "=r"(r[1]), "=r"(r[2]), "=r"(r[3]) : "r"(a));
}

__device__ __forceinline__ void mma16816(float* c, const uint32_t* a, const uint32_t* b) {
    asm volatile(
        "mma.sync.aligned.m16n8k16.row.col.f32.bf16.bf16.f32 "
        "{%0,%1,%2,%3}, {%4,%5,%6,%7}, {%8,%9}, {%0,%1,%2,%3};"
        : "+f"(c[0]), "+f"(c[1]), "+f"(c[2]), "+f"(c[3])
        : "r"(a[0]), "r"(a[1]), "r"(a[2]), "r"(a[3]), "r"(b[0]), "r"(b[1]));
}

__device__ __forceinline__ void cp16(uint32_t dst, const void* src) {
    asm volatile("cp.async.cg.shared.global [%0], [%1], 16;"
                 :: "r"(dst), "l"(src) : "memory");
}
#define CP_COMMIT asm volatile("cp.async.commit_group;" ::: "memory")
#define CP_WAIT0  asm volatile("cp.async.wait_group 0;"  ::: "memory")

__device__ __forceinline__ uint32_t pack2(__nv_bfloat16 a, __nv_bfloat16 b) {
    __nv_bfloat162 t = __halves2bfloat162(a, b);
    return *(uint32_t*)&t;
}

// ===========================================================================
// Split-convert fp32 -> bf16 hi + bf16 lo
// ===========================================================================
__global__ void convert_split(const float* __restrict__ src, int which, int n4)
{
    __nv_bfloat16 *hi, *lo;
    switch (which) {
        case 0: hi = g_xhi;    lo = g_xlo;    break;
        case 1: hi = g_whi[0]; lo = g_wlo[0]; break;
        case 2: hi = g_whi[1]; lo = g_wlo[1]; break;
        case 3: hi = g_whi[2]; lo = g_wlo[2]; break;
        default: hi = g_whi[3]; lo = g_wlo[3]; break;
    }
    for (int i = blockIdx.x * blockDim.x + threadIdx.x; i < n4;
         i += gridDim.x * blockDim.x) {
        float4 v = ((const float4*)src)[i];
        __nv_bfloat16 h0 = __float2bfloat16(v.x);
        __nv_bfloat16 h1 = __float2bfloat16(v.y);
        __nv_bfloat16 h2 = __float2bfloat16(v.z);
        __nv_bfloat16 h3 = __float2bfloat16(v.w);
        uint2 ho = make_uint2(pack2(h0, h1), pack2(h2, h3));
        __nv_bfloat16 l0 = __float2bfloat16(v.x - __bfloat162float(h0));
        __nv_bfloat16 l1 = __float2bfloat16(v.y - __bfloat162float(h1));
        __nv_bfloat16 l2 = __float2bfloat16(v.z - __bfloat162float(h2));
        __nv_bfloat16 l3 = __float2bfloat16(v.w - __bfloat162float(h3));
        uint2 lov = make_uint2(pack2(l0, l1), pack2(l2, l3));
        ((uint2*)hi)[i] = ho;
        ((uint2*)lo)[i] = lov;
    }
}

// ===========================================================================
// mma.sync GEMM mainloop (3-term split, TERM-OUTER ordering -> no RAW chains)
// ===========================================================================
#define PITCH_H     40
#define TILE_B      (128*PITCH_H*2)     // 10240
#define STAGE_B     (4*TILE_B)          // 40960
#define GSMEM       (2*STAGE_B)         // 81920

__device__ __forceinline__ void gemm_mainloop(
    const __nv_bfloat16* __restrict__ Ahi, const __nv_bfloat16* __restrict__ Alo,
    const __nv_bfloat16* __restrict__ Bhi, const __nv_bfloat16* __restrict__ Blo,
    int m0, int n0, char* sm, float acc[4][4][4])
{
    const int tid = threadIdx.x;
    const uint32_t smb = smem_u32(sm);

    #pragma unroll
    for (int t = 0; t < 4; t++)
        #pragma unroll
        for (int n = 0; n < 4; n++)
            #pragma unroll
            for (int e = 0; e < 4; e++) acc[t][n][e] = 0.0f;

    auto load_stage = [&](int st, int k0) {
        uint32_t base = smb + st * STAGE_B;
        #pragma unroll
        for (int j = 0; j < 2; j++) {
            int idx = tid + j * 256;
            int r = idx >> 2, c = idx & 3;
            uint32_t doff = r * (PITCH_H*2) + c * 16;
            size_t sa = (size_t)(m0 + r) * DD + k0 + c * 8;
            size_t sb = (size_t)(n0 + r) * DD + k0 + c * 8;
            cp16(base + doff,            Ahi + sa);
            cp16(base + TILE_B + doff,   Alo + sa);
            cp16(base + 2*TILE_B + doff, Bhi + sb);
            cp16(base + 3*TILE_B + doff, Blo + sb);
        }
    };

    load_stage(0, 0);
    CP_COMMIT;

    const int wid = tid >> 5, lane = tid & 31;
    const int wm = (wid >> 2) * 64;
    const int wn = (wid & 3) * 32;
    const int arow = lane & 15;
    const int akk  = (lane >> 4) << 3;
    const int brow = (lane & 7) + ((lane >> 4) << 3);
    const int bkk  = ((lane >> 3) & 1) << 3;

    for (int kt = 0; kt < 32; kt++) {
        CP_WAIT0;
        __syncthreads();
        if (kt + 1 < 32) { load_stage((kt + 1) & 1, (kt + 1) * 32); CP_COMMIT; }

        uint32_t base = smb + (kt & 1) * STAGE_B;
        uint32_t sAh = base, sAl = base + TILE_B;
        uint32_t sBh = base + 2*TILE_B, sBl = base + 3*TILE_B;

        #pragma unroll
        for (int k16 = 0; k16 < 2; k16++) {
            const int ko = k16 * 16;
            uint32_t ah[4][4], al[4][4], bh[4][2], bl[4][2];
            #pragma unroll
            for (int t = 0; t < 4; t++) {
                uint32_t ao = (uint32_t)((wm + t*16 + arow) * (PITCH_H*2) + (ko + akk) * 2);
                ldsm4(ah[t], sAh + ao);
                ldsm4(al[t], sAl + ao);
            }
            #pragma unroll
            for (int p = 0; p < 2; p++) {
                uint32_t bo = (uint32_t)((wn + p*16 + brow) * (PITCH_H*2) + (ko + bkk) * 2);
                uint32_t r4[4];
                ldsm4(r4, sBh + bo);
                bh[2*p][0] = r4[0]; bh[2*p][1] = r4[1];
                bh[2*p+1][0] = r4[2]; bh[2*p+1][1] = r4[3];
                ldsm4(r4, sBl + bo);
                bl[2*p][0] = r4[0]; bl[2*p][1] = r4[1];
                bl[2*p+1][0] = r4[2]; bl[2*p+1][1] = r4[3];
            }
            // term-outer: 16 independent accumulators between revisits
            #pragma unroll
            for (int t = 0; t < 4; t++)
                #pragma unroll
                for (int n = 0; n < 4; n++)
                    mma16816(acc[t][n], ah[t], bh[n]);
            #pragma unroll
            for (int t = 0; t < 4; t++)
                #pragma unroll
                for (int n = 0; n < 4; n++)
                    mma16816(acc[t][n], ah[t], bl[n]);
            #pragma unroll
            for (int t = 0; t < 4; t++)
                #pragma unroll
                for (int n = 0; n < 4; n++)
                    mma16816(acc[t][n], al[t], bh[n]);
        }
    }
}

// ---------------------------------------------------------------------------
__global__ __launch_bounds__(256) void qkv_gemm_mma()
{
    extern __shared__ char sm[];
    const int n0g = blockIdx.x * 128;
    const int m0  = blockIdx.y * 128;
    const int which = n0g >> 10;
    const int nb    = n0g & 1023;

    float* OUT = (which == 0) ? g_q : (which == 1 ? g_k : g_v);

    float acc[4][4][4];
    gemm_mainloop(g_xhi, g_xlo, g_whi[which], g_wlo[which], m0, nb, sm, acc);

    const int tid = threadIdx.x, wid = tid >> 5, lane = tid & 31;
    const int wm = (wid >> 2) * 64, wn = (wid & 3) * 32;
    const int gid = lane >> 2, qid = lane & 3;

    #pragma unroll
    for (int t = 0; t < 4; t++) {
        #pragma unroll
        for (int n = 0; n < 4; n++) {
            int cc = nb + wn + n*8 + qid*2;
            int h = cc >> 6, hd = cc & 63;
            #pragma unroll
            for (int half = 0; half < 2; half++) {
                int row = m0 + wm + t*16 + gid + 8*half;
                int b = row >> 11, s = row & 2047;
                float2 v = make_float2(acc[t][n][2*half], acc[t][n][2*half + 1]);
                *(float2*)&OUT[(((size_t)(b*NH + h))*SB + s)*HDIM + hd] = v;
            }
        }
    }
}

// ---------------------------------------------------------------------------
__global__ __launch_bounds__(256) void out_gemm_mma(
    const float* __restrict__ bo, float* __restrict__ OUT)
{
    extern __shared__ char sm[];
    const int n0 = blockIdx.x * 128;
    const int m0 = blockIdx.y * 128;

    float acc[4][4][4];
    gemm_mainloop(g_chi, g_clo, g_whi[3], g_wlo[3], m0, n0, sm, acc);

    const int tid = threadIdx.x, wid = tid >> 5, lane = tid & 31;
    const int wm = (wid >> 2) * 64, wn = (wid & 3) * 32;
    const int gid = lane >> 2, qid = lane & 3;

    #pragma unroll
    for (int t = 0; t < 4; t++) {
        #pragma unroll
        for (int n = 0; n < 4; n++) {
            int cn = n0 + wn + n*8 + qid*2;
            float2 bb = *(const float2*)&bo[cn];
            #pragma unroll
            for (int half = 0; half < 2; half++) {
                int row = m0 + wm + t*16 + gid + 8*half;
                float2 v = make_float2(acc[t][n][2*half] + bb.x,
                                       acc[t][n][2*half + 1] + bb.y);
                *(float2*)&OUT[(size_t)row * DD + cn] = v;
            }
        }
    }
}

// ===========================================================================
// Flash attention: 128x128 tiles, 8x8 per-thread S-tile, float4 smem loads.
// Thread (tx,ty) 16x16 grid: q rows ty+16i (i<8), s cols tx+16j (j<8),
// o cols tx+16j (j<4). Pitches chosen conflict-free under LDS.128 phases.
// ===========================================================================
#define QPITCH 68
#define VPITCH 132
#define PPITCH 132
#define FA_SMEM ((2*128*QPITCH + 64*VPITCH + 128*PPITCH) * 4)  // 171008 B

__global__ __launch_bounds__(256) void flash_attn()
{
    extern __shared__ char smc[];
    float* Qs = (float*)smc;              // [128][68]
    float* Ks = Qs + 128*QPITCH;          // [128][68]
    float* Vt = Ks + 128*QPITCH;          // [64][132]  (transposed: [d][c])
    float* Ps = Vt + 64*VPITCH;           // [128][132]

    const int qt = (int)gridDim.x - 1 - (int)blockIdx.x;   // heavy tiles first
    const int bh = blockIdx.y;
    const int q0 = qt * 128;

    const float* __restrict__ Qp = g_q + ((size_t)bh*SB + q0)*HDIM;
    const float* __restrict__ Kp = g_k + (size_t)bh*SB*HDIM;
    const float* __restrict__ Vp = g_v + (size_t)bh*SB*HDIM;

    const int tid = threadIdx.x;
    const int tx = tid & 15, ty = tid >> 4;

    // Load Q tile (resident)
    for (int idx = tid; idx < 2048; idx += 256) {
        int r = idx >> 4, c4 = idx & 15;
        *(float4*)&Qs[r*QPITCH + c4*4] = *(const float4*)(Qp + r*64 + c4*4);
    }

    float m_i[8], l_i[8], o[8][4];
    #pragma unroll
    for (int i = 0; i < 8; i++) {
        m_i[i] = -INFINITY; l_i[i] = 0.0f;
        #pragma unroll
        for (int j = 0; j < 4; j++) o[i][j] = 0.0f;
    }

    for (int kt = 0; kt <= qt; kt++) {
        const int c0 = kt * 128;
        __syncthreads();   // Ks/Vt/Ps free from previous iteration

        // K coalesced
        for (int idx = tid; idx < 2048; idx += 256) {
            int r = idx >> 4, c4 = idx & 15;
            *(float4*)&Ks[r*QPITCH + c4*4] =
                *(const float4*)(Kp + (size_t)(c0 + r)*64 + c4*4);
        }
        // V transposed (conflict-free STS; gmem strided but L2-resident)
        for (int idx = tid; idx < 2048; idx += 256) {
            int c = idx & 127, d4 = idx >> 7;
            float4 v = *(const float4*)(Vp + (size_t)(c0 + c)*64 + d4*4);
            Vt[(d4*4+0)*VPITCH + c] = v.x;
            Vt[(d4*4+1)*VPITCH + c] = v.y;
            Vt[(d4*4+2)*VPITCH + c] = v.z;
            Vt[(d4*4+3)*VPITCH + c] = v.w;
        }
        __syncthreads();

        // S = Q K^T (128x128x64)
        float s[8][8];
        #pragma unroll
        for (int i = 0; i < 8; i++)
            #pragma unroll
            for (int j = 0; j < 8; j++) s[i][j] = 0.0f;

        #pragma unroll 2
        for (int d4 = 0; d4 < 16; d4++) {
            float4 k4[8];
            #pragma unroll
            for (int j = 0; j < 8; j++)
                k4[j] = *(const float4*)&Ks[(tx + 16*j)*QPITCH + d4*4];
            #pragma unroll
            for (int i = 0; i < 8; i++) {
                float4 q4 = *(const float4*)&Qs[(ty + 16*i)*QPITCH + d4*4];
                #pragma unroll
                for (int j = 0; j < 8; j++) {
                    s[i][j] = fmaf(q4.x, k4[j].x, s[i][j]);
                    s[i][j] = fmaf(q4.y, k4[j].y, s[i][j]);
                    s[i][j] = fmaf(q4.z, k4[j].z, s[i][j]);
                    s[i][j] = fmaf(q4.w, k4[j].w, s[i][j]);
                }
            }
        }

        // scale + causal mask
        const bool diag = (kt == qt);
        #pragma unroll
        for (int i = 0; i < 8; i++) {
            int r = ty + 16*i;
            #pragma unroll
            for (int j = 0; j < 8; j++) {
                int c = tx + 16*j;
                float sv = s[i][j] * 0.125f;
                if (diag && c > r) sv = -INFINITY;
                s[i][j] = sv;
            }
        }

        // online softmax (reduce across 16 tx lanes)
        float rm[8], rs[8];
        #pragma unroll
        for (int i = 0; i < 8; i++) {
            rm[i] = s[i][0];
            #pragma unroll
            for (int j = 1; j < 8; j++) rm[i] = fmaxf(rm[i], s[i][j]);
        }
        #pragma unroll
        for (int msk = 8; msk >= 1; msk >>= 1)
            #pragma unroll
            for (int i = 0; i < 8; i++)
                rm[i] = fmaxf(rm[i], __shfl_xor_sync(0xffffffffu, rm[i], msk));
        #pragma unroll
        for (int i = 0; i < 8; i++) {
            float mn = fmaxf(m_i[i], rm[i]);
            float al = __expf(m_i[i] - mn);
            m_i[i] = mn;
            rs[i] = 0.0f;
            #pragma unroll
            for (int j = 0; j < 8; j++) {
                s[i][j] = __expf(s[i][j] - mn);
                rs[i] += s[i][j];
            }
            l_i[i] = l_i[i] * al;
            #pragma unroll
            for (int j = 0; j < 4; j++) o[i][j] *= al;
        }
        #pragma unroll
        for (int msk = 8; msk >= 1; msk >>= 1)
            #pragma unroll
            for (int i = 0; i < 8; i++)
                rs[i] += __shfl_xor_sync(0xffffffffu, rs[i], msk);
        #pragma unroll
        for (int i = 0; i < 8; i++) {
            l_i[i] += rs[i];
            #pragma unroll
            for (int j = 0; j < 8; j++)
                Ps[(ty + 16*i)*PPITCH + tx + 16*j] = s[i][j];
        }
        __syncthreads();

        // O += P V (128x64x128)
        #pragma unroll 2
        for (int c4 = 0; c4 < 32; c4++) {
            float4 v4[4];
            #pragma unroll
            for (int j = 0; j < 4; j++)
                v4[j] = *(const float4*)&Vt[(tx + 16*j)*VPITCH + c4*4];
            #pragma unroll
            for (int i = 0; i < 8; i++) {
                float4 p4 = *(const float4*)&Ps[(ty + 16*i)*PPITCH + c4*4];
                #pragma unroll
                for (int j = 0; j < 4; j++) {
                    o[i][j] = fmaf(p4.x, v4[j].x, o[i][j]);
                    o[i][j] = fmaf(p4.y, v4[j].y, o[i][j]);
                    o[i][j] = fmaf(p4.z, v4[j].z, o[i][j]);
                    o[i][j] = fmaf(p4.w, v4[j].w, o[i][j]);
                }
            }
        }
    }

    // finalize + write ctx as bf16 hi/lo (feeds out projection)
    const int b = bh / NH, h = bh % NH;
    #pragma unroll
    for (int i = 0; i < 8; i++) {
        int r = ty + 16*i;
        float inv = 1.0f / l_i[i];
        #pragma unroll
        for (int j = 0; j < 4; j++) {
            int dd = tx + 16*j;
            float val = o[i][j] * inv;
            __nv_bfloat16 hh = __float2bfloat16(val);
            __nv_bfloat16 ll = __float2bfloat16(val - __bfloat162float(hh));
            size_t off = ((size_t)(b*SB + q0 + r))*DD + h*HDIM + dd;
            g_chi[off] = hh;
            g_clo[off] = ll;
        }
    }
}

// ---------------------------------------------------------------------------
extern "C" void kernel_launch(void* const* d_in, const int* in_sizes, int n_in,
                              void* d_out, int out_size)
{
    const float* x  = (const float*)d_in[0];
    const float* Wq = (const float*)d_in[1];
    const float* Wk = (const float*)d_in[2];
    const float* Wv = (const float*)d_in[3];
    const float* Wo = (const float*)d_in[4];
    const float* bo = (const float*)d_in[5];
    float* out = (float*)d_out;

    cudaFuncSetAttribute(qkv_gemm_mma, cudaFuncAttributeMaxDynamicSharedMemorySize, GSMEM);
    cudaFuncSetAttribute(out_gemm_mma, cudaFuncAttributeMaxDynamicSharedMemorySize, GSMEM);
    cudaFuncSetAttribute(flash_attn,   cudaFuncAttributeMaxDynamicSharedMemorySize, FA_SMEM);

    convert_split<<<512, 256>>>(x,  0, MR*DD/4);
    convert_split<<<256, 256>>>(Wq, 1, DD*DD/4);
    convert_split<<<256, 256>>>(Wk, 2, DD*DD/4);
    convert_split<<<256, 256>>>(Wv, 3, DD*DD/4);
    convert_split<<<256, 256>>>(Wo, 4, DD*DD/4);

    qkv_gemm_mma<<<dim3(24, 32), 256, GSMEM>>>();
    flash_attn<<<dim3(SB/128, BB*NH), 256, FA_SMEM>>>();
    out_gemm_mma<<<dim3(8, 32), 256, GSMEM>>>(bo, out);
}

// round 5
// speedup vs baseline: 1.8445x; 1.0168x over previous
#include <cuda_runtime.h>
#include <cuda_bf16.h>
#include <math.h>
#include <stdint.h>

// Problem constants
#define SB   2048
#define BB   2
#define DD   1024
#define NH   16
#define HDIM 64
#define MR   (BB*SB)       // 4096

// Scratch (device globals) — all attention tensors live as bf16 hi/lo splits
__device__ __align__(256) __nv_bfloat16 g_xhi[(size_t)MR*DD];
__device__ __align__(256) __nv_bfloat16 g_xlo[(size_t)MR*DD];
__device__ __align__(256) __nv_bfloat16 g_whi[4][(size_t)DD*DD];
__device__ __align__(256) __nv_bfloat16 g_wlo[4][(size_t)DD*DD];
__device__ __align__(256) __nv_bfloat16 g_qhi[(size_t)MR*DD];   // [b,h,s,hd]
__device__ __align__(256) __nv_bfloat16 g_qlo[(size_t)MR*DD];
__device__ __align__(256) __nv_bfloat16 g_khi[(size_t)MR*DD];
__device__ __align__(256) __nv_bfloat16 g_klo[(size_t)MR*DD];
__device__ __align__(256) __nv_bfloat16 g_vhi[(size_t)MR*DD];
__device__ __align__(256) __nv_bfloat16 g_vlo[(size_t)MR*DD];
__device__ __align__(256) __nv_bfloat16 g_chi[(size_t)MR*DD];   // ctx [b,s,d]
__device__ __align__(256) __nv_bfloat16 g_clo[(size_t)MR*DD];

// ===========================================================================
// Helpers
// ===========================================================================
__device__ __forceinline__ uint32_t smem_u32(const void* p) {
    uint32_t a;
    asm("{ .reg .u64 t; cvta.to.shared.u64 t, %1; cvt.u32.u64 %0, t; }"
        : "=r"(a) : "l"(p));
    return a;
}

__device__ __forceinline__ void ldsm4(uint32_t* r, uint32_t a) {
    asm volatile("ldmatrix.sync.aligned.m8n8.x4.shared.b16 {%0,%1,%2,%3}, [%4];"
                 : "=r"(r[0]), "=r"(r[1]), "=r"(r[2]), "=r"(r[3]) : "r"(a));
}

__device__ __forceinline__ void ldsm4t(uint32_t* r, uint32_t a) {
    asm volatile("ldmatrix.sync.aligned.m8n8.x4.trans.shared.b16 {%0,%1,%2,%3}, [%4];"
                 : "=r"(r[0]), "=r"(r[1]), "=r"(r[2]), "=r"(r[3]) : "r"(a));
}

__device__ __forceinline__ void mma16816(float* c, const uint32_t* a, const uint32_t* b) {
    asm volatile(
        "mma.sync.aligned.m16n8k16.row.col.f32.bf16.bf16.f32 "
        "{%0,%1,%2,%3}, {%4,%5,%6,%7}, {%8,%9}, {%0,%1,%2,%3};"
        : "+f"(c[0]), "+f"(c[1]), "+f"(c[2]), "+f"(c[3])
        : "r"(a[0]), "r"(a[1]), "r"(a[2]), "r"(a[3]), "r"(b[0]), "r"(b[1]));
}

__device__ __forceinline__ void cp16(uint32_t dst, const void* src) {
    asm volatile("cp.async.cg.shared.global [%0], [%1], 16;"
                 :: "r"(dst), "l"(src) : "memory");
}
#define CP_COMMIT asm volatile("cp.async.commit_group;" ::: "memory")
#define CP_WAIT0  asm volatile("cp.async.wait_group 0;"  ::: "memory")
#define CP_WAIT1  asm volatile("cp.async.wait_group 1;"  ::: "memory")

__device__ __forceinline__ uint32_t pack2(__nv_bfloat16 a, __nv_bfloat16 b) {
    __nv_bfloat162 t = __halves2bfloat162(a, b);
    return *(uint32_t*)&t;
}

// pack hi pair, return lo pair by reference
__device__ __forceinline__ uint32_t packsplit(float a, float b, uint32_t& lo) {
    __nv_bfloat16 ha = __float2bfloat16(a), hb = __float2bfloat16(b);
    lo = pack2(__float2bfloat16(a - __bfloat162float(ha)),
               __float2bfloat16(b - __bfloat162float(hb)));
    return pack2(ha, hb);
}

// ===========================================================================
// Split-convert fp32 -> bf16 hi + lo (one launch, 5 segments)
// ===========================================================================
__global__ void convert_split_all(const float* __restrict__ x,
                                  const float* __restrict__ Wq,
                                  const float* __restrict__ Wk,
                                  const float* __restrict__ Wv,
                                  const float* __restrict__ Wo)
{
    const int seg = blockIdx.y;
    const float* src;
    __nv_bfloat16 *hi, *lo;
    int n4;
    switch (seg) {
        case 0: src = x;  hi = g_xhi;    lo = g_xlo;    n4 = MR*DD/4; break;
        case 1: src = Wq; hi = g_whi[0]; lo = g_wlo[0]; n4 = DD*DD/4; break;
        case 2: src = Wk; hi = g_whi[1]; lo = g_wlo[1]; n4 = DD*DD/4; break;
        case 3: src = Wv; hi = g_whi[2]; lo = g_wlo[2]; n4 = DD*DD/4; break;
        default: src = Wo; hi = g_whi[3]; lo = g_wlo[3]; n4 = DD*DD/4; break;
    }
    for (int i = blockIdx.x * blockDim.x + threadIdx.x; i < n4;
         i += gridDim.x * blockDim.x) {
        float4 v = ((const float4*)src)[i];
        uint32_t l01, l23;
        uint32_t h01 = packsplit(v.x, v.y, l01);
        uint32_t h23 = packsplit(v.z, v.w, l23);
        ((uint2*)hi)[i] = make_uint2(h01, h23);
        ((uint2*)lo)[i] = make_uint2(l01, l23);
    }
}

// ===========================================================================
// mma.sync GEMM mainloop (3-term split, term-outer ordering)
// ===========================================================================
#define PITCH_H     40
#define TILE_B      (128*PITCH_H*2)     // 10240
#define STAGE_B     (4*TILE_B)          // 40960
#define GSMEM       (2*STAGE_B)         // 81920

__device__ __forceinline__ void gemm_mainloop(
    const __nv_bfloat16* __restrict__ Ahi, const __nv_bfloat16* __restrict__ Alo,
    const __nv_bfloat16* __restrict__ Bhi, const __nv_bfloat16* __restrict__ Blo,
    int m0, int n0, char* sm, float acc[4][4][4])
{
    const int tid = threadIdx.x;
    const uint32_t smb = smem_u32(sm);

    #pragma unroll
    for (int t = 0; t < 4; t++)
        #pragma unroll
        for (int n = 0; n < 4; n++)
            #pragma unroll
            for (int e = 0; e < 4; e++) acc[t][n][e] = 0.0f;

    auto load_stage = [&](int st, int k0) {
        uint32_t base = smb + st * STAGE_B;
        #pragma unroll
        for (int j = 0; j < 2; j++) {
            int idx = tid + j * 256;
            int r = idx >> 2, c = idx & 3;
            uint32_t doff = r * (PITCH_H*2) + c * 16;
            size_t sa = (size_t)(m0 + r) * DD + k0 + c * 8;
            size_t sb = (size_t)(n0 + r) * DD + k0 + c * 8;
            cp16(base + doff,            Ahi + sa);
            cp16(base + TILE_B + doff,   Alo + sa);
            cp16(base + 2*TILE_B + doff, Bhi + sb);
            cp16(base + 3*TILE_B + doff, Blo + sb);
        }
    };

    load_stage(0, 0);
    CP_COMMIT;

    const int wid = tid >> 5, lane = tid & 31;
    const int wm = (wid >> 2) * 64;
    const int wn = (wid & 3) * 32;
    const int arow = lane & 15;
    const int akk  = (lane >> 4) << 3;
    const int brow = (lane & 7) + ((lane >> 4) << 3);
    const int bkk  = ((lane >> 3) & 1) << 3;

    for (int kt = 0; kt < 32; kt++) {
        CP_WAIT0;
        __syncthreads();
        if (kt + 1 < 32) { load_stage((kt + 1) & 1, (kt + 1) * 32); CP_COMMIT; }

        uint32_t base = smb + (kt & 1) * STAGE_B;
        uint32_t sAh = base, sAl = base + TILE_B;
        uint32_t sBh = base + 2*TILE_B, sBl = base + 3*TILE_B;

        #pragma unroll
        for (int k16 = 0; k16 < 2; k16++) {
            const int ko = k16 * 16;
            uint32_t ah[4][4], al[4][4], bh[4][2], bl[4][2];
            #pragma unroll
            for (int t = 0; t < 4; t++) {
                uint32_t ao = (uint32_t)((wm + t*16 + arow) * (PITCH_H*2) + (ko + akk) * 2);
                ldsm4(ah[t], sAh + ao);
                ldsm4(al[t], sAl + ao);
            }
            #pragma unroll
            for (int p = 0; p < 2; p++) {
                uint32_t bo = (uint32_t)((wn + p*16 + brow) * (PITCH_H*2) + (ko + bkk) * 2);
                uint32_t r4[4];
                ldsm4(r4, sBh + bo);
                bh[2*p][0] = r4[0]; bh[2*p][1] = r4[1];
                bh[2*p+1][0] = r4[2]; bh[2*p+1][1] = r4[3];
                ldsm4(r4, sBl + bo);
                bl[2*p][0] = r4[0]; bl[2*p][1] = r4[1];
                bl[2*p+1][0] = r4[2]; bl[2*p+1][1] = r4[3];
            }
            #pragma unroll
            for (int t = 0; t < 4; t++)
                #pragma unroll
                for (int n = 0; n < 4; n++)
                    mma16816(acc[t][n], ah[t], bh[n]);
            #pragma unroll
            for (int t = 0; t < 4; t++)
                #pragma unroll
                for (int n = 0; n < 4; n++)
                    mma16816(acc[t][n], ah[t], bl[n]);
            #pragma unroll
            for (int t = 0; t < 4; t++)
                #pragma unroll
                for (int n = 0; n < 4; n++)
                    mma16816(acc[t][n], al[t], bh[n]);
        }
    }
}

// ---------------------------------------------------------------------------
// QKV projection: writes q/k/v as bf16 hi/lo in [b,h,s,hd]
// ---------------------------------------------------------------------------
__global__ __launch_bounds__(256) void qkv_gemm_mma()
{
    extern __shared__ char sm[];
    const int n0g = blockIdx.x * 128;
    const int m0  = blockIdx.y * 128;
    const int which = n0g >> 10;
    const int nb    = n0g & 1023;

    __nv_bfloat16* OH = (which == 0) ? g_qhi : (which == 1 ? g_khi : g_vhi);
    __nv_bfloat16* OL = (which == 0) ? g_qlo : (which == 1 ? g_klo : g_vlo);

    float acc[4][4][4];
    gemm_mainloop(g_xhi, g_xlo, g_whi[which], g_wlo[which], m0, nb, sm, acc);

    const int tid = threadIdx.x, wid = tid >> 5, lane = tid & 31;
    const int wm = (wid >> 2) * 64, wn = (wid & 3) * 32;
    const int gid = lane >> 2, qid = lane & 3;

    #pragma unroll
    for (int t = 0; t < 4; t++) {
        #pragma unroll
        for (int n = 0; n < 4; n++) {
            int cc = nb + wn + n*8 + qid*2;
            int h = cc >> 6, hd = cc & 63;
            #pragma unroll
            for (int half = 0; half < 2; half++) {
                int row = m0 + wm + t*16 + gid + 8*half;
                int b = row >> 11, s = row & 2047;
                uint32_t lo;
                uint32_t hi = packsplit(acc[t][n][2*half], acc[t][n][2*half+1], lo);
                size_t off = (((size_t)(b*NH + h))*SB + s)*HDIM + hd;
                *(uint32_t*)&OH[off] = hi;
                *(uint32_t*)&OL[off] = lo;
            }
        }
    }
}

// ---------------------------------------------------------------------------
// Output projection: out = ctx @ Wo^T + bo (fp32 out)
// ---------------------------------------------------------------------------
__global__ __launch_bounds__(256) void out_gemm_mma(
    const float* __restrict__ bo, float* __restrict__ OUT)
{
    extern __shared__ char sm[];
    const int n0 = blockIdx.x * 128;
    const int m0 = blockIdx.y * 128;

    float acc[4][4][4];
    gemm_mainloop(g_chi, g_clo, g_whi[3], g_wlo[3], m0, n0, sm, acc);

    const int tid = threadIdx.x, wid = tid >> 5, lane = tid & 31;
    const int wm = (wid >> 2) * 64, wn = (wid & 3) * 32;
    const int gid = lane >> 2, qid = lane & 3;

    #pragma unroll
    for (int t = 0; t < 4; t++) {
        #pragma unroll
        for (int n = 0; n < 4; n++) {
            int cn = n0 + wn + n*8 + qid*2;
            float2 bb = *(const float2*)&bo[cn];
            #pragma unroll
            for (int half = 0; half < 2; half++) {
                int row = m0 + wm + t*16 + gid + 8*half;
                float2 v = make_float2(acc[t][n][2*half] + bb.x,
                                       acc[t][n][2*half + 1] + bb.y);
                *(float2*)&OUT[(size_t)row * DD + cn] = v;
            }
        }
    }
}

// ===========================================================================
// Flash attention on mma.sync (FA2-style, 3-term bf16 split).
// 128 q-rows per CTA (8 warps x 16 rows), 64-key steps, double-buffered KV.
// ===========================================================================
#define FP_B  144                    // smem pitch bytes (72 halves)
#define QH_OFF 0
#define QL_OFF (128*FP_B)            // 18432
#define ST_OFF (2*128*FP_B)          // 36864
#define BUF_B  (64*FP_B)             // 9216
#define STG_B  (4*BUF_B)             // 36864
#define FA_SMEM (ST_OFF + 2*STG_B)   // 110592

__global__ __launch_bounds__(256) void flash_attn_mma()
{
    extern __shared__ char smc[];
    const uint32_t smb = smem_u32(smc);

    const int qt = (int)gridDim.x - 1 - (int)blockIdx.x;   // heavy first
    const int bh = blockIdx.y;
    const int q0 = qt * 128;

    const int tid = threadIdx.x, w = tid >> 5, lane = tid & 31;
    const int wm = w * 16;

    const __nv_bfloat16* Qph = g_qhi + ((size_t)bh*SB + q0)*HDIM;
    const __nv_bfloat16* Qpl = g_qlo + ((size_t)bh*SB + q0)*HDIM;
    const __nv_bfloat16* Kph = g_khi + (size_t)bh*SB*HDIM;
    const __nv_bfloat16* Kpl = g_klo + (size_t)bh*SB*HDIM;
    const __nv_bfloat16* Vph = g_vhi + (size_t)bh*SB*HDIM;
    const __nv_bfloat16* Vpl = g_vlo + (size_t)bh*SB*HDIM;

    // ---- load Q (hi+lo) ----
    for (int idx = tid; idx < 2048; idx += 256) {
        int buf = idx >> 10, r = (idx >> 3) & 127, c = idx & 7;
        cp16(smb + (buf ? QL_OFF : QH_OFF) + r*FP_B + c*16,
             (buf ? Qpl : Qph) + r*64 + c*8);
    }
    CP_COMMIT;

    auto load_kv = [&](int st, int c0) {
        uint32_t base = smb + ST_OFF + st*STG_B;
        for (int idx = tid; idx < 2048; idx += 256) {
            int buf = idx >> 9, r = (idx >> 3) & 63, c = idx & 7;
            const __nv_bfloat16* sp =
                (buf == 0 ? Kph : buf == 1 ? Kpl : buf == 2 ? Vph : Vpl)
                + (size_t)(c0 + r)*64 + c*8;
            cp16(base + buf*BUF_B + r*FP_B + c*16, sp);
        }
    };

    const int nsteps = 2*(qt + 1);
    load_kv(0, 0);
    CP_COMMIT;

    // wait Q only (1 pending group allowed), build resident Q fragments
    CP_WAIT1;
    __syncthreads();

    const int arow = lane & 15;
    const int akk  = (lane >> 4) << 3;
    uint32_t qa[2][4][4];
    #pragma unroll
    for (int term = 0; term < 2; term++)
        #pragma unroll
        for (int t = 0; t < 4; t++)
            ldsm4(qa[term][t], smb + (term ? QL_OFF : QH_OFF)
                              + (wm + arow)*FP_B + (t*16 + akk)*2);

    float m0v = -INFINITY, m1v = -INFINITY, l0v = 0.0f, l1v = 0.0f;
    float oc[8][4];
    #pragma unroll
    for (int j = 0; j < 8; j++)
        #pragma unroll
        for (int e = 0; e < 4; e++) oc[j][e] = 0.0f;

    const int brow = (lane & 7) + ((lane >> 4) << 3);
    const int bkk  = ((lane >> 3) & 1) << 3;
    const int vrow = (lane & 7) + (((lane >> 3) & 1) << 3);
    const int vc8  = (lane >> 4) << 3;

    for (int kt = 0; kt < nsteps; kt++) {
        const int c0 = kt * 64;
        CP_WAIT0;
        __syncthreads();
        if (kt + 1 < nsteps) { load_kv((kt + 1) & 1, (kt + 1)*64); CP_COMMIT; }

        const uint32_t sKh = smb + ST_OFF + (kt & 1)*STG_B;
        const uint32_t sKl = sKh + BUF_B;
        const uint32_t sVh = sKh + 2*BUF_B;
        const uint32_t sVl = sKh + 3*BUF_B;

        // ---- S = Q K^T ----
        float sc[8][4];
        #pragma unroll
        for (int j = 0; j < 8; j++)
            #pragma unroll
            for (int e = 0; e < 4; e++) sc[j][e] = 0.0f;

        #pragma unroll
        for (int k16 = 0; k16 < 4; k16++) {
            uint32_t kh[8][2], kl[8][2];
            #pragma unroll
            for (int j2 = 0; j2 < 4; j2++) {
                uint32_t off = (uint32_t)((j2*16 + brow)*FP_B + (k16*16 + bkk)*2);
                uint32_t r4[4];
                ldsm4(r4, sKh + off);
                kh[2*j2][0] = r4[0]; kh[2*j2][1] = r4[1];
                kh[2*j2+1][0] = r4[2]; kh[2*j2+1][1] = r4[3];
                ldsm4(r4, sKl + off);
                kl[2*j2][0] = r4[0]; kl[2*j2][1] = r4[1];
                kl[2*j2+1][0] = r4[2]; kl[2*j2+1][1] = r4[3];
            }
            #pragma unroll
            for (int j = 0; j < 8; j++) mma16816(sc[j], qa[0][k16], kh[j]);
            #pragma unroll
            for (int j = 0; j < 8; j++) mma16816(sc[j], qa[0][k16], kl[j]);
            #pragma unroll
            for (int j = 0; j < 8; j++) mma16816(sc[j], qa[1][k16], kh[j]);
        }

        // ---- scale + causal mask ----
        const int r0 = q0 + wm + (lane >> 2);
        const bool needmask = (c0 + 64 > q0 + wm);
        #pragma unroll
        for (int j = 0; j < 8; j++) {
            int cb = c0 + j*8 + (lane & 3)*2;
            #pragma unroll
            for (int e = 0; e < 4; e++) {
                float v = sc[j][e] * 0.125f;
                if (needmask) {
                    int col = cb + (e & 1);
                    int row = r0 + ((e >> 1) << 3);
                    if (col > row) v = -INFINITY;
                }
                sc[j][e] = v;
            }
        }

        // ---- online softmax (rows r0, r0+8; quad reduce over lane&3) ----
        float mx0 = sc[0][0], mx1 = sc[0][2];
        #pragma unroll
        for (int j = 0; j < 8; j++) {
            mx0 = fmaxf(mx0, fmaxf(sc[j][0], sc[j][1]));
            mx1 = fmaxf(mx1, fmaxf(sc[j][2], sc[j][3]));
        }
        mx0 = fmaxf(mx0, __shfl_xor_sync(0xffffffffu, mx0, 1));
        mx0 = fmaxf(mx0, __shfl_xor_sync(0xffffffffu, mx0, 2));
        mx1 = fmaxf(mx1, __shfl_xor_sync(0xffffffffu, mx1, 1));
        mx1 = fmaxf(mx1, __shfl_xor_sync(0xffffffffu, mx1, 2));

        float mn0 = fmaxf(m0v, mx0), mn1 = fmaxf(m1v, mx1);
        float al0 = __expf(m0v - mn0), al1 = __expf(m1v - mn1);
        m0v = mn0; m1v = mn1;

        float s0 = 0.0f, s1 = 0.0f;
        #pragma unroll
        for (int j = 0; j < 8; j++) {
            sc[j][0] = __expf(sc[j][0] - mn0); s0 += sc[j][0];
            sc[j][1] = __expf(sc[j][1] - mn0); s0 += sc[j][1];
            sc[j][2] = __expf(sc[j][2] - mn1); s1 += sc[j][2];
            sc[j][3] = __expf(sc[j][3] - mn1); s1 += sc[j][3];
        }
        s0 += __shfl_xor_sync(0xffffffffu, s0, 1);
        s0 += __shfl_xor_sync(0xffffffffu, s0, 2);
        s1 += __shfl_xor_sync(0xffffffffu, s1, 1);
        s1 += __shfl_xor_sync(0xffffffffu, s1, 2);
        l0v = l0v * al0 + s0;
        l1v = l1v * al1 + s1;
        #pragma unroll
        for (int j = 0; j < 8; j++) {
            oc[j][0] *= al0; oc[j][1] *= al0;
            oc[j][2] *= al1; oc[j][3] *= al1;
        }

        // ---- repack P (C-frag == A-frag layout) ----
        uint32_t pah[4][4], pal[4][4];
        #pragma unroll
        for (int t = 0; t < 4; t++) {
            pah[t][0] = packsplit(sc[2*t][0],   sc[2*t][1],   pal[t][0]);
            pah[t][1] = packsplit(sc[2*t][2],   sc[2*t][3],   pal[t][1]);
            pah[t][2] = packsplit(sc[2*t+1][0], sc[2*t+1][1], pal[t][2]);
            pah[t][3] = packsplit(sc[2*t+1][2], sc[2*t+1][3], pal[t][3]);
        }

        // ---- O += P V ----
        #pragma unroll
        for (int k16 = 0; k16 < 4; k16++) {
            uint32_t vh[8][2], vl[8][2];
            #pragma unroll
            for (int n16 = 0; n16 < 4; n16++) {
                uint32_t off = (uint32_t)((k16*16 + vrow)*FP_B + (n16*16 + vc8)*2);
                uint32_t r4[4];
                ldsm4t(r4, sVh + off);
                vh[2*n16][0] = r4[0]; vh[2*n16][1] = r4[1];
                vh[2*n16+1][0] = r4[2]; vh[2*n16+1][1] = r4[3];
                ldsm4t(r4, sVl + off);
                vl[2*n16][0] = r4[0]; vl[2*n16][1] = r4[1];
                vl[2*n16+1][0] = r4[2]; vl[2*n16+1][1] = r4[3];
            }
            #pragma unroll
            for (int j = 0; j < 8; j++) mma16816(oc[j], pah[k16], vh[j]);
            #pragma unroll
            for (int j = 0; j < 8; j++) mma16816(oc[j], pah[k16], vl[j]);
            #pragma unroll
            for (int j = 0; j < 8; j++) mma16816(oc[j], pal[k16], vh[j]);
        }
    }

    // ---- finalize, write ctx bf16 hi/lo ----
    const float inv0 = 1.0f / l0v, inv1 = 1.0f / l1v;
    const int b = bh / NH, h = bh % NH;
    const int row0 = q0 + wm + (lane >> 2);
    #pragma unroll
    for (int j = 0; j < 8; j++) {
        int col = h*64 + j*8 + (lane & 3)*2;
        uint32_t lo;
        uint32_t hi = packsplit(oc[j][0]*inv0, oc[j][1]*inv0, lo);
        size_t off0 = ((size_t)(b*SB + row0))*DD + col;
        *(uint32_t*)&g_chi[off0] = hi;
        *(uint32_t*)&g_clo[off0] = lo;
        hi = packsplit(oc[j][2]*inv1, oc[j][3]*inv1, lo);
        size_t off1 = ((size_t)(b*SB + row0 + 8))*DD + col;
        *(uint32_t*)&g_chi[off1] = hi;
        *(uint32_t*)&g_clo[off1] = lo;
    }
}

// ---------------------------------------------------------------------------
extern "C" void kernel_launch(void* const* d_in, const int* in_sizes, int n_in,
                              void* d_out, int out_size)
{
    const float* x  = (const float*)d_in[0];
    const float* Wq = (const float*)d_in[1];
    const float* Wk = (const float*)d_in[2];
    const float* Wv = (const float*)d_in[3];
    const float* Wo = (const float*)d_in[4];
    const float* bo = (const float*)d_in[5];
    float* out = (float*)d_out;

    cudaFuncSetAttribute(qkv_gemm_mma,  cudaFuncAttributeMaxDynamicSharedMemorySize, GSMEM);
    cudaFuncSetAttribute(out_gemm_mma,  cudaFuncAttributeMaxDynamicSharedMemorySize, GSMEM);
    cudaFuncSetAttribute(flash_attn_mma, cudaFuncAttributeMaxDynamicSharedMemorySize, FA_SMEM);

    convert_split_all<<<dim3(160, 5), 256>>>(x, Wq, Wk, Wv, Wo);
    qkv_gemm_mma<<<dim3(24, 32), 256, GSMEM>>>();
    flash_attn_mma<<<dim3(SB/128, BB*NH), 256, FA_SMEM>>>();
    out_gemm_mma<<<dim3(8, 32), 256, GSMEM>>>(bo, out);
}

// round 6
// speedup vs baseline: 3.0699x; 1.6643x over previous
#include <cuda_runtime.h>
#include <cuda_bf16.h>
#include <math.h>
#include <stdint.h>

// Problem constants
#define SB   2048
#define BB   2
#define DD   1024
#define NH   16
#define HDIM 64
#define MR   (BB*SB)       // 4096

// Scratch (device globals) — all attention tensors live as bf16 hi/lo splits
__device__ __align__(256) __nv_bfloat16 g_xhi[(size_t)MR*DD];
__device__ __align__(256) __nv_bfloat16 g_xlo[(size_t)MR*DD];
__device__ __align__(256) __nv_bfloat16 g_whi[4][(size_t)DD*DD];
__device__ __align__(256) __nv_bfloat16 g_wlo[4][(size_t)DD*DD];
__device__ __align__(256) __nv_bfloat16 g_qhi[(size_t)MR*DD];   // [b,h,s,hd]
__device__ __align__(256) __nv_bfloat16 g_qlo[(size_t)MR*DD];
__device__ __align__(256) __nv_bfloat16 g_khi[(size_t)MR*DD];
__device__ __align__(256) __nv_bfloat16 g_klo[(size_t)MR*DD];
__device__ __align__(256) __nv_bfloat16 g_vhi[(size_t)MR*DD];
__device__ __align__(256) __nv_bfloat16 g_vlo[(size_t)MR*DD];
__device__ __align__(256) __nv_bfloat16 g_chi[(size_t)MR*DD];   // ctx [b,s,d]
__device__ __align__(256) __nv_bfloat16 g_clo[(size_t)MR*DD];

// ===========================================================================
// Helpers
// ===========================================================================
__device__ __forceinline__ uint32_t smem_u32(const void* p) {
    uint32_t a;
    asm("{ .reg .u64 t; cvta.to.shared.u64 t, %1; cvt.u32.u64 %0, t; }"
        : "=r"(a) : "l"(p));
    return a;
}

__device__ __forceinline__ void ldsm4(uint32_t* r, uint32_t a) {
    asm volatile("ldmatrix.sync.aligned.m8n8.x4.shared.b16 {%0,%1,%2,%3}, [%4];"
                 : "=r"(r[0]), "=r"(r[1]), "=r"(r[2]), "=r"(r[3]) : "r"(a));
}

__device__ __forceinline__ void ldsm4t(uint32_t* r, uint32_t a) {
    asm volatile("ldmatrix.sync.aligned.m8n8.x4.trans.shared.b16 {%0,%1,%2,%3}, [%4];"
                 : "=r"(r[0]), "=r"(r[1]), "=r"(r[2]), "=r"(r[3]) : "r"(a));
}

__device__ __forceinline__ void mma16816(float* c, const uint32_t* a, const uint32_t* b) {
    asm volatile(
        "mma.sync.aligned.m16n8k16.row.col.f32.bf16.bf16.f32 "
        "{%0,%1,%2,%3}, {%4,%5,%6,%7}, {%8,%9}, {%0,%1,%2,%3};"
        : "+f"(c[0]), "+f"(c[1]), "+f"(c[2]), "+f"(c[3])
        : "r"(a[0]), "r"(a[1]), "r"(a[2]), "r"(a[3]), "r"(b[0]), "r"(b[1]));
}

__device__ __forceinline__ void cp16(uint32_t dst, const void* src) {
    asm volatile("cp.async.cg.shared.global [%0], [%1], 16;"
                 :: "r"(dst), "l"(src) : "memory");
}
#define CP_COMMIT asm volatile("cp.async.commit_group;" ::: "memory")
#define CP_WAIT0  asm volatile("cp.async.wait_group 0;"  ::: "memory")
#define CP_WAIT1  asm volatile("cp.async.wait_group 1;"  ::: "memory")

__device__ __forceinline__ uint32_t pack2(__nv_bfloat16 a, __nv_bfloat16 b) {
    __nv_bfloat162 t = __halves2bfloat162(a, b);
    return *(uint32_t*)&t;
}

__device__ __forceinline__ uint32_t packsplit(float a, float b, uint32_t& lo) {
    __nv_bfloat16 ha = __float2bfloat16(a), hb = __float2bfloat16(b);
    lo = pack2(__float2bfloat16(a - __bfloat162float(ha)),
               __float2bfloat16(b - __bfloat162float(hb)));
    return pack2(ha, hb);
}

// ===========================================================================
// Split-convert fp32 -> bf16 hi + lo (one launch, 5 segments)
// ===========================================================================
__global__ void convert_split_all(const float* __restrict__ x,
                                  const float* __restrict__ Wq,
                                  const float* __restrict__ Wk,
                                  const float* __restrict__ Wv,
                                  const float* __restrict__ Wo)
{
    const int seg = blockIdx.y;
    const float* src;
    __nv_bfloat16 *hi, *lo;
    int n4;
    switch (seg) {
        case 0: src = x;  hi = g_xhi;    lo = g_xlo;    n4 = MR*DD/4; break;
        case 1: src = Wq; hi = g_whi[0]; lo = g_wlo[0]; n4 = DD*DD/4; break;
        case 2: src = Wk; hi = g_whi[1]; lo = g_wlo[1]; n4 = DD*DD/4; break;
        case 3: src = Wv; hi = g_whi[2]; lo = g_wlo[2]; n4 = DD*DD/4; break;
        default: src = Wo; hi = g_whi[3]; lo = g_wlo[3]; n4 = DD*DD/4; break;
    }
    for (int i = blockIdx.x * blockDim.x + threadIdx.x; i < n4;
         i += gridDim.x * blockDim.x) {
        float4 v = ((const float4*)src)[i];
        uint32_t l01, l23;
        uint32_t h01 = packsplit(v.x, v.y, l01);
        uint32_t h23 = packsplit(v.z, v.w, l23);
        ((uint2*)hi)[i] = make_uint2(h01, h23);
        ((uint2*)lo)[i] = make_uint2(l01, l23);
    }
}

// ===========================================================================
// mma.sync GEMM mainloop (3-term split, term-outer ordering)
// ===========================================================================
#define PITCH_H     40
#define TILE_B      (128*PITCH_H*2)     // 10240
#define STAGE_B     (4*TILE_B)          // 40960
#define GSMEM       (2*STAGE_B)         // 81920

__device__ __forceinline__ void gemm_mainloop(
    const __nv_bfloat16* __restrict__ Ahi, const __nv_bfloat16* __restrict__ Alo,
    const __nv_bfloat16* __restrict__ Bhi, const __nv_bfloat16* __restrict__ Blo,
    int m0, int n0, char* sm, float acc[4][4][4])
{
    const int tid = threadIdx.x;
    const uint32_t smb = smem_u32(sm);

    #pragma unroll
    for (int t = 0; t < 4; t++)
        #pragma unroll
        for (int n = 0; n < 4; n++)
            #pragma unroll
            for (int e = 0; e < 4; e++) acc[t][n][e] = 0.0f;

    auto load_stage = [&](int st, int k0) {
        uint32_t base = smb + st * STAGE_B;
        #pragma unroll
        for (int j = 0; j < 2; j++) {
            int idx = tid + j * 256;
            int r = idx >> 2, c = idx & 3;
            uint32_t doff = r * (PITCH_H*2) + c * 16;
            size_t sa = (size_t)(m0 + r) * DD + k0 + c * 8;
            size_t sb = (size_t)(n0 + r) * DD + k0 + c * 8;
            cp16(base + doff,            Ahi + sa);
            cp16(base + TILE_B + doff,   Alo + sa);
            cp16(base + 2*TILE_B + doff, Bhi + sb);
            cp16(base + 3*TILE_B + doff, Blo + sb);
        }
    };

    load_stage(0, 0);
    CP_COMMIT;

    const int wid = tid >> 5, lane = tid & 31;
    const int wm = (wid >> 2) * 64;
    const int wn = (wid & 3) * 32;
    const int arow = lane & 15;
    const int akk  = (lane >> 4) << 3;
    const int brow = (lane & 7) + ((lane >> 4) << 3);
    const int bkk  = ((lane >> 3) & 1) << 3;

    for (int kt = 0; kt < 32; kt++) {
        CP_WAIT0;
        __syncthreads();
        if (kt + 1 < 32) { load_stage((kt + 1) & 1, (kt + 1) * 32); CP_COMMIT; }

        uint32_t base = smb + (kt & 1) * STAGE_B;
        uint32_t sAh = base, sAl = base + TILE_B;
        uint32_t sBh = base + 2*TILE_B, sBl = base + 3*TILE_B;

        #pragma unroll
        for (int k16 = 0; k16 < 2; k16++) {
            const int ko = k16 * 16;
            uint32_t ah[4][4], al[4][4], bh[4][2], bl[4][2];
            #pragma unroll
            for (int t = 0; t < 4; t++) {
                uint32_t ao = (uint32_t)((wm + t*16 + arow) * (PITCH_H*2) + (ko + akk) * 2);
                ldsm4(ah[t], sAh + ao);
                ldsm4(al[t], sAl + ao);
            }
            #pragma unroll
            for (int p = 0; p < 2; p++) {
                uint32_t bo = (uint32_t)((wn + p*16 + brow) * (PITCH_H*2) + (ko + bkk) * 2);
                uint32_t r4[4];
                ldsm4(r4, sBh + bo);
                bh[2*p][0] = r4[0]; bh[2*p][1] = r4[1];
                bh[2*p+1][0] = r4[2]; bh[2*p+1][1] = r4[3];
                ldsm4(r4, sBl + bo);
                bl[2*p][0] = r4[0]; bl[2*p][1] = r4[1];
                bl[2*p+1][0] = r4[2]; bl[2*p+1][1] = r4[3];
            }
            #pragma unroll
            for (int t = 0; t < 4; t++)
                #pragma unroll
                for (int n = 0; n < 4; n++)
                    mma16816(acc[t][n], ah[t], bh[n]);
            #pragma unroll
            for (int t = 0; t < 4; t++)
                #pragma unroll
                for (int n = 0; n < 4; n++)
                    mma16816(acc[t][n], ah[t], bl[n]);
            #pragma unroll
            for (int t = 0; t < 4; t++)
                #pragma unroll
                for (int n = 0; n < 4; n++)
                    mma16816(acc[t][n], al[t], bh[n]);
        }
    }
}

// ---------------------------------------------------------------------------
// QKV projection: writes q/k/v as bf16 hi/lo in [b,h,s,hd]
// ---------------------------------------------------------------------------
__global__ __launch_bounds__(256, 2) void qkv_gemm_mma()
{
    extern __shared__ char sm[];
    const int n0g = blockIdx.x * 128;
    const int m0  = blockIdx.y * 128;
    const int which = n0g >> 10;
    const int nb    = n0g & 1023;

    __nv_bfloat16* OH = (which == 0) ? g_qhi : (which == 1 ? g_khi : g_vhi);
    __nv_bfloat16* OL = (which == 0) ? g_qlo : (which == 1 ? g_klo : g_vlo);

    float acc[4][4][4];
    gemm_mainloop(g_xhi, g_xlo, g_whi[which], g_wlo[which], m0, nb, sm, acc);

    const int tid = threadIdx.x, wid = tid >> 5, lane = tid & 31;
    const int wm = (wid >> 2) * 64, wn = (wid & 3) * 32;
    const int gid = lane >> 2, qid = lane & 3;

    #pragma unroll
    for (int t = 0; t < 4; t++) {
        #pragma unroll
        for (int n = 0; n < 4; n++) {
            int cc = nb + wn + n*8 + qid*2;
            int h = cc >> 6, hd = cc & 63;
            #pragma unroll
            for (int half = 0; half < 2; half++) {
                int row = m0 + wm + t*16 + gid + 8*half;
                int b = row >> 11, s = row & 2047;
                uint32_t lo;
                uint32_t hi = packsplit(acc[t][n][2*half], acc[t][n][2*half+1], lo);
                size_t off = (((size_t)(b*NH + h))*SB + s)*HDIM + hd;
                *(uint32_t*)&OH[off] = hi;
                *(uint32_t*)&OL[off] = lo;
            }
        }
    }
}

// ---------------------------------------------------------------------------
// Output projection: out = ctx @ Wo^T + bo (fp32 out)
// ---------------------------------------------------------------------------
__global__ __launch_bounds__(256, 2) void out_gemm_mma(
    const float* __restrict__ bo, float* __restrict__ OUT)
{
    extern __shared__ char sm[];
    const int n0 = blockIdx.x * 128;
    const int m0 = blockIdx.y * 128;

    float acc[4][4][4];
    gemm_mainloop(g_chi, g_clo, g_whi[3], g_wlo[3], m0, n0, sm, acc);

    const int tid = threadIdx.x, wid = tid >> 5, lane = tid & 31;
    const int wm = (wid >> 2) * 64, wn = (wid & 3) * 32;
    const int gid = lane >> 2, qid = lane & 3;

    #pragma unroll
    for (int t = 0; t < 4; t++) {
        #pragma unroll
        for (int n = 0; n < 4; n++) {
            int cn = n0 + wn + n*8 + qid*2;
            float2 bb = *(const float2*)&bo[cn];
            #pragma unroll
            for (int half = 0; half < 2; half++) {
                int row = m0 + wm + t*16 + gid + 8*half;
                float2 v = make_float2(acc[t][n][2*half] + bb.x,
                                       acc[t][n][2*half + 1] + bb.y);
                *(float2*)&OUT[(size_t)row * DD + cn] = v;
            }
        }
    }
}

// ===========================================================================
// Flash attention on mma.sync (FA2-style, 3-term bf16 split).
// 128 q-rows per CTA (8 warps x 16 rows), 64-key steps.
// SMEM: two 36864B regions, ping-pong KV stages. Q loads into region B and
// is consumed into register fragments before kt=1 overwrites region B.
// ===========================================================================
#define FP_B  144                    // smem pitch bytes (72 halves)
#define BUF_B  (64*FP_B)             // 9216
#define STG_B  (4*BUF_B)             // 36864
#define FA_SMEM (2*STG_B)            // 73728

__global__ __launch_bounds__(256, 2) void flash_attn_mma()
{
    extern __shared__ char smc[];
    const uint32_t smb = smem_u32(smc);

    const int qt = (int)gridDim.x - 1 - (int)blockIdx.x;   // heavy first
    const int bh = blockIdx.y;
    const int q0 = qt * 128;

    const int tid = threadIdx.x, w = tid >> 5, lane = tid & 31;
    const int wm = w * 16;

    const __nv_bfloat16* Qph = g_qhi + ((size_t)bh*SB + q0)*HDIM;
    const __nv_bfloat16* Qpl = g_qlo + ((size_t)bh*SB + q0)*HDIM;
    const __nv_bfloat16* Kph = g_khi + (size_t)bh*SB*HDIM;
    const __nv_bfloat16* Kpl = g_klo + (size_t)bh*SB*HDIM;
    const __nv_bfloat16* Vph = g_vhi + (size_t)bh*SB*HDIM;
    const __nv_bfloat16* Vpl = g_vlo + (size_t)bh*SB*HDIM;

    // ---- load Q (hi+lo) into region B (offset STG_B) ----
    const uint32_t QH_OFF = STG_B;
    const uint32_t QL_OFF = STG_B + 128*FP_B;
    for (int idx = tid; idx < 2048; idx += 256) {
        int buf = idx >> 10, r = (idx >> 3) & 127, c = idx & 7;
        cp16(smb + (buf ? QL_OFF : QH_OFF) + r*FP_B + c*16,
             (buf ? Qpl : Qph) + r*64 + c*8);
    }
    CP_COMMIT;

    auto load_kv = [&](int st, int c0) {
        uint32_t base = smb + st*STG_B;
        for (int idx = tid; idx < 2048; idx += 256) {
            int buf = idx >> 9, r = (idx >> 3) & 63, c = idx & 7;
            const __nv_bfloat16* sp =
                (buf == 0 ? Kph : buf == 1 ? Kpl : buf == 2 ? Vph : Vpl)
                + (size_t)(c0 + r)*64 + c*8;
            cp16(base + buf*BUF_B + r*FP_B + c*16, sp);
        }
    };

    const int nsteps = 2*(qt + 1);
    load_kv(0, 0);     // region A
    CP_COMMIT;

    // wait Q only (1 pending group allowed), build resident Q fragments
    CP_WAIT1;
    __syncthreads();

    const int arow = lane & 15;
    const int akk  = (lane >> 4) << 3;
    uint32_t qa[2][4][4];
    #pragma unroll
    for (int term = 0; term < 2; term++)
        #pragma unroll
        for (int t = 0; t < 4; t++)
            ldsm4(qa[term][t], smb + (term ? QL_OFF : QH_OFF)
                              + (wm + arow)*FP_B + (t*16 + akk)*2);

    float m0v = -INFINITY, m1v = -INFINITY, l0v = 0.0f, l1v = 0.0f;
    float oc[8][4];
    #pragma unroll
    for (int j = 0; j < 8; j++)
        #pragma unroll
        for (int e = 0; e < 4; e++) oc[j][e] = 0.0f;

    const int brow = (lane & 7) + ((lane >> 4) << 3);
    const int bkk  = ((lane >> 3) & 1) << 3;
    const int vrow = (lane & 7) + (((lane >> 3) & 1) << 3);
    const int vc8  = (lane >> 4) << 3;

    for (int kt = 0; kt < nsteps; kt++) {
        const int c0 = kt * 64;
        CP_WAIT0;
        __syncthreads();
        if (kt + 1 < nsteps) { load_kv((kt + 1) & 1, (kt + 1)*64); CP_COMMIT; }

        const uint32_t sKh = smb + (kt & 1)*STG_B;
        const uint32_t sKl = sKh + BUF_B;
        const uint32_t sVh = sKh + 2*BUF_B;
        const uint32_t sVl = sKh + 3*BUF_B;

        // ---- S = Q K^T ----
        float sc[8][4];
        #pragma unroll
        for (int j = 0; j < 8; j++)
            #pragma unroll
            for (int e = 0; e < 4; e++) sc[j][e] = 0.0f;

        #pragma unroll
        for (int k16 = 0; k16 < 4; k16++) {
            uint32_t kh[8][2], kl[8][2];
            #pragma unroll
            for (int j2 = 0; j2 < 4; j2++) {
                uint32_t off = (uint32_t)((j2*16 + brow)*FP_B + (k16*16 + bkk)*2);
                uint32_t r4[4];
                ldsm4(r4, sKh + off);
                kh[2*j2][0] = r4[0]; kh[2*j2][1] = r4[1];
                kh[2*j2+1][0] = r4[2]; kh[2*j2+1][1] = r4[3];
                ldsm4(r4, sKl + off);
                kl[2*j2][0] = r4[0]; kl[2*j2][1] = r4[1];
                kl[2*j2+1][0] = r4[2]; kl[2*j2+1][1] = r4[3];
            }
            #pragma unroll
            for (int j = 0; j < 8; j++) mma16816(sc[j], qa[0][k16], kh[j]);
            #pragma unroll
            for (int j = 0; j < 8; j++) mma16816(sc[j], qa[0][k16], kl[j]);
            #pragma unroll
            for (int j = 0; j < 8; j++) mma16816(sc[j], qa[1][k16], kh[j]);
        }

        // ---- scale + causal mask ----
        const int r0 = q0 + wm + (lane >> 2);
        const bool needmask = (c0 + 64 > q0 + wm);
        #pragma unroll
        for (int j = 0; j < 8; j++) {
            int cb = c0 + j*8 + (lane & 3)*2;
            #pragma unroll
            for (int e = 0; e < 4; e++) {
                float v = sc[j][e] * 0.125f;
                if (needmask) {
                    int col = cb + (e & 1);
                    int row = r0 + ((e >> 1) << 3);
                    if (col > row) v = -INFINITY;
                }
                sc[j][e] = v;
            }
        }

        // ---- online softmax (rows r0, r0+8; quad reduce over lane&3) ----
        float mx0 = sc[0][0], mx1 = sc[0][2];
        #pragma unroll
        for (int j = 0; j < 8; j++) {
            mx0 = fmaxf(mx0, fmaxf(sc[j][0], sc[j][1]));
            mx1 = fmaxf(mx1, fmaxf(sc[j][2], sc[j][3]));
        }
        mx0 = fmaxf(mx0, __shfl_xor_sync(0xffffffffu, mx0, 1));
        mx0 = fmaxf(mx0, __shfl_xor_sync(0xffffffffu, mx0, 2));
        mx1 = fmaxf(mx1, __shfl_xor_sync(0xffffffffu, mx1, 1));
        mx1 = fmaxf(mx1, __shfl_xor_sync(0xffffffffu, mx1, 2));

        float mn0 = fmaxf(m0v, mx0), mn1 = fmaxf(m1v, mx1);
        float al0 = __expf(m0v - mn0), al1 = __expf(m1v - mn1);
        m0v = mn0; m1v = mn1;

        float s0 = 0.0f, s1 = 0.0f;
        #pragma unroll
        for (int j = 0; j < 8; j++) {
            sc[j][0] = __expf(sc[j][0] - mn0); s0 += sc[j][0];
            sc[j][1] = __expf(sc[j][1] - mn0); s0 += sc[j][1];
            sc[j][2] = __expf(sc[j][2] - mn1); s1 += sc[j][2];
            sc[j][3] = __expf(sc[j][3] - mn1); s1 += sc[j][3];
        }
        s0 += __shfl_xor_sync(0xffffffffu, s0, 1);
        s0 += __shfl_xor_sync(0xffffffffu, s0, 2);
        s1 += __shfl_xor_sync(0xffffffffu, s1, 1);
        s1 += __shfl_xor_sync(0xffffffffu, s1, 2);
        l0v = l0v * al0 + s0;
        l1v = l1v * al1 + s1;
        #pragma unroll
        for (int j = 0; j < 8; j++) {
            oc[j][0] *= al0; oc[j][1] *= al0;
            oc[j][2] *= al1; oc[j][3] *= al1;
        }

        // ---- repack P (C-frag == A-frag layout) ----
        uint32_t pah[4][4], pal[4][4];
        #pragma unroll
        for (int t = 0; t < 4; t++) {
            pah[t][0] = packsplit(sc[2*t][0],   sc[2*t][1],   pal[t][0]);
            pah[t][1] = packsplit(sc[2*t][2],   sc[2*t][3],   pal[t][1]);
            pah[t][2] = packsplit(sc[2*t+1][0], sc[2*t+1][1], pal[t][2]);
            pah[t][3] = packsplit(sc[2*t+1][2], sc[2*t+1][3], pal[t][3]);
        }

        // ---- O += P V ----
        #pragma unroll
        for (int k16 = 0; k16 < 4; k16++) {
            uint32_t vh[8][2], vl[8][2];
            #pragma unroll
            for (int n16 = 0; n16 < 4; n16++) {
                uint32_t off = (uint32_t)((k16*16 + vrow)*FP_B + (n16*16 + vc8)*2);
                uint32_t r4[4];
                ldsm4t(r4, sVh + off);
                vh[2*n16][0] = r4[0]; vh[2*n16][1] = r4[1];
                vh[2*n16+1][0] = r4[2]; vh[2*n16+1][1] = r4[3];
                ldsm4t(r4, sVl + off);
                vl[2*n16][0] = r4[0]; vl[2*n16][1] = r4[1];
                vl[2*n16+1][0] = r4[2]; vl[2*n16+1][1] = r4[3];
            }
            #pragma unroll
            for (int j = 0; j < 8; j++) mma16816(oc[j], pah[k16], vh[j]);
            #pragma unroll
            for (int j = 0; j < 8; j++) mma16816(oc[j], pah[k16], vl[j]);
            #pragma unroll
            for (int j = 0; j < 8; j++) mma16816(oc[j], pal[k16], vh[j]);
        }
    }

    // ---- finalize, write ctx bf16 hi/lo ----
    const float inv0 = 1.0f / l0v, inv1 = 1.0f / l1v;
    const int b = bh / NH, h = bh % NH;
    const int row0 = q0 + wm + (lane >> 2);
    #pragma unroll
    for (int j = 0; j < 8; j++) {
        int col = h*64 + j*8 + (lane & 3)*2;
        uint32_t lo;
        uint32_t hi = packsplit(oc[j][0]*inv0, oc[j][1]*inv0, lo);
        size_t off0 = ((size_t)(b*SB + row0))*DD + col;
        *(uint32_t*)&g_chi[off0] = hi;
        *(uint32_t*)&g_clo[off0] = lo;
        hi = packsplit(oc[j][2]*inv1, oc[j][3]*inv1, lo);
        size_t off1 = ((size_t)(b*SB + row0 + 8))*DD + col;
        *(uint32_t*)&g_chi[off1] = hi;
        *(uint32_t*)&g_clo[off1] = lo;
    }
}

// ---------------------------------------------------------------------------
extern "C" void kernel_launch(void* const* d_in, const int* in_sizes, int n_in,
                              void* d_out, int out_size)
{
    const float* x  = (const float*)d_in[0];
    const float* Wq = (const float*)d_in[1];
    const float* Wk = (const float*)d_in[2];
    const float* Wv = (const float*)d_in[3];
    const float* Wo = (const float*)d_in[4];
    const float* bo = (const float*)d_in[5];
    float* out = (float*)d_out;

    cudaFuncSetAttribute(qkv_gemm_mma,  cudaFuncAttributeMaxDynamicSharedMemorySize, GSMEM);
    cudaFuncSetAttribute(out_gemm_mma,  cudaFuncAttributeMaxDynamicSharedMemorySize, GSMEM);
    cudaFuncSetAttribute(flash_attn_mma, cudaFuncAttributeMaxDynamicSharedMemorySize, FA_SMEM);

    convert_split_all<<<dim3(160, 5), 256>>>(x, Wq, Wk, Wv, Wo);
    qkv_gemm_mma<<<dim3(24, 32), 256, GSMEM>>>();
    flash_attn_mma<<<dim3(SB/128, BB*NH), 256, FA_SMEM>>>();
    out_gemm_mma<<<dim3(8, 32), 256, GSMEM>>>(bo, out);
}